// round 11
// baseline (speedup 1.0000x reference)
#include <cuda_runtime.h>
#include <cstdint>

// Submanifold 3x3 conv (cross-correlation, SAME) on independent 4x4x1 tiles.
// ONE THREAD PER TILE (64B): 2x LDG.256 in, 2x STG.256 out. No shuffles, no
// edge selects — tile edges are compile-time zeros. Rows (0,1) and (2,3) are
// computed together with packed fma.rn.f32x2; the "below" packs of the first
// block are reused as the "above" packs of the second.

__device__ __forceinline__ unsigned long long pk2(float lo, float hi) {
    unsigned long long r;
    asm("mov.b64 %0, {%1, %2};" : "=l"(r) : "f"(lo), "f"(hi));
    return r;
}
__device__ __forceinline__ unsigned long long fma2(
    unsigned long long a, unsigned long long b, unsigned long long c) {
    unsigned long long d;
    asm("fma.rn.f32x2 %0, %1, %2, %3;" : "=l"(d) : "l"(a), "l"(b), "l"(c));
    return d;
}
__device__ __forceinline__ unsigned long long mul2(
    unsigned long long a, unsigned long long b) {
    unsigned long long d;
    asm("mul.rn.f32x2 %0, %1, %2;" : "=l"(d) : "l"(a), "l"(b));
    return d;
}
__device__ __forceinline__ void upk2(unsigned long long v, float& lo, float& hi) {
    asm("mov.b64 {%0, %1}, %2;" : "=f"(lo), "=f"(hi) : "l"(v));
}

// One packed 2-row conv block. P0/P1/P2 are (above,mid0 | mid0,mid1 | mid1,below)
// packs; writes the two packed output rows via S0..S3 -> (oA[j], oB[j]).
__device__ __forceinline__ void conv_block(
    const unsigned long long P0[4], const unsigned long long P1[4],
    const unsigned long long P2[4], const unsigned long long ww[9],
    float oA[4], float oB[4])
{
    unsigned long long S0, S1, S2, S3;
    // j = 0 (window cols 1,2)
    S0 = mul2(P0[0], ww[1]);
    S0 = fma2(P1[0], ww[4], S0);
    S0 = fma2(P2[0], ww[7], S0);
    S0 = fma2(P0[1], ww[2], S0);
    S0 = fma2(P1[1], ww[5], S0);
    S0 = fma2(P2[1], ww[8], S0);
    // j = 1
    S1 = mul2(P0[0], ww[0]);
    S1 = fma2(P1[0], ww[3], S1);
    S1 = fma2(P2[0], ww[6], S1);
    S1 = fma2(P0[1], ww[1], S1);
    S1 = fma2(P1[1], ww[4], S1);
    S1 = fma2(P2[1], ww[7], S1);
    S1 = fma2(P0[2], ww[2], S1);
    S1 = fma2(P1[2], ww[5], S1);
    S1 = fma2(P2[2], ww[8], S1);
    // j = 2
    S2 = mul2(P0[1], ww[0]);
    S2 = fma2(P1[1], ww[3], S2);
    S2 = fma2(P2[1], ww[6], S2);
    S2 = fma2(P0[2], ww[1], S2);
    S2 = fma2(P1[2], ww[4], S2);
    S2 = fma2(P2[2], ww[7], S2);
    S2 = fma2(P0[3], ww[2], S2);
    S2 = fma2(P1[3], ww[5], S2);
    S2 = fma2(P2[3], ww[8], S2);
    // j = 3 (window cols 0,1)
    S3 = mul2(P0[2], ww[0]);
    S3 = fma2(P1[2], ww[3], S3);
    S3 = fma2(P2[2], ww[6], S3);
    S3 = fma2(P0[3], ww[1], S3);
    S3 = fma2(P1[3], ww[4], S3);
    S3 = fma2(P2[3], ww[7], S3);

    upk2(S0, oA[0], oB[0]);
    upk2(S1, oA[1], oB[1]);
    upk2(S2, oA[2], oB[2]);
    upk2(S3, oA[3], oB[3]);
}

__global__ __launch_bounds__(256) void subm_conv_tile_v8_kernel(
    const float* __restrict__ x,
    const float* __restrict__ W,
    float* __restrict__ y,
    int n_tiles)
{
    int gid = blockIdx.x * blockDim.x + threadIdx.x;
    if (gid >= n_tiles) return;

    // Two independent 256-bit streaming loads: the whole 4x4 tile.
    const float* xin = x + 16 * (size_t)gid;
    float r0[4], r1[4], r2[4], r3[4];
    asm("ld.global.cs.v8.f32 {%0,%1,%2,%3,%4,%5,%6,%7}, [%8];"
        : "=f"(r0[0]), "=f"(r0[1]), "=f"(r0[2]), "=f"(r0[3]),
          "=f"(r1[0]), "=f"(r1[1]), "=f"(r1[2]), "=f"(r1[3])
        : "l"(xin));
    asm("ld.global.cs.v8.f32 {%0,%1,%2,%3,%4,%5,%6,%7}, [%8];"
        : "=f"(r2[0]), "=f"(r2[1]), "=f"(r2[2]), "=f"(r2[3]),
          "=f"(r3[0]), "=f"(r3[1]), "=f"(r3[2]), "=f"(r3[3])
        : "l"(xin + 8));

    // Broadcast weight loads (uniform address -> L1 broadcast hits).
    float4 w03 = __ldg(reinterpret_cast<const float4*>(W));
    float4 w47 = __ldg(reinterpret_cast<const float4*>(W) + 1);
    float  w8f = __ldg(W + 8);

    unsigned long long ww[9];
    ww[0] = pk2(w03.x, w03.x);
    ww[1] = pk2(w03.y, w03.y);
    ww[2] = pk2(w03.z, w03.z);
    ww[3] = pk2(w03.w, w03.w);
    ww[4] = pk2(w47.x, w47.x);
    ww[5] = pk2(w47.y, w47.y);
    ww[6] = pk2(w47.z, w47.z);
    ww[7] = pk2(w47.w, w47.w);
    ww[8] = pk2(w8f,  w8f);

    // Block A: output rows (0,1). Above rows = (zero, r0); mid = (r0, r1);
    // below = (r1, r2).
    unsigned long long PA0[4], PA1[4], PA2[4];
#pragma unroll
    for (int c = 0; c < 4; c++) {
        PA0[c] = pk2(0.0f,  r0[c]);
        PA1[c] = pk2(r0[c], r1[c]);
        PA2[c] = pk2(r1[c], r2[c]);
    }

    float o0[4], o1[4];
    conv_block(PA0, PA1, PA2, ww, o0, o1);

    // Block B: output rows (2,3). Above = (r1, r2) == PA2 (reused);
    // mid = (r2, r3); below = (r3, zero).
    unsigned long long PB1[4], PB2[4];
#pragma unroll
    for (int c = 0; c < 4; c++) {
        PB1[c] = pk2(r2[c], r3[c]);
        PB2[c] = pk2(r3[c], 0.0f);
    }

    float o2[4], o3[4];
    conv_block(PA2, PB1, PB2, ww, o2, o3);

    // Submanifold mask: write only at active (nonzero-input) sites.
#pragma unroll
    for (int j = 0; j < 4; j++) {
        o0[j] = (r0[j] != 0.0f) ? o0[j] : 0.0f;
        o1[j] = (r1[j] != 0.0f) ? o1[j] : 0.0f;
        o2[j] = (r2[j] != 0.0f) ? o2[j] : 0.0f;
        o3[j] = (r3[j] != 0.0f) ? o3[j] : 0.0f;
    }

    // Two 256-bit stores: the whole output tile.
    float* yout = y + 16 * (size_t)gid;
    asm volatile("st.global.v8.f32 [%0], {%1,%2,%3,%4,%5,%6,%7,%8};"
        :: "l"(yout),
           "f"(o0[0]), "f"(o0[1]), "f"(o0[2]), "f"(o0[3]),
           "f"(o1[0]), "f"(o1[1]), "f"(o1[2]), "f"(o1[3])
        : "memory");
    asm volatile("st.global.v8.f32 [%0], {%1,%2,%3,%4,%5,%6,%7,%8};"
        :: "l"(yout + 8),
           "f"(o2[0]), "f"(o2[1]), "f"(o2[2]), "f"(o2[3]),
           "f"(o3[0]), "f"(o3[1]), "f"(o3[2]), "f"(o3[3])
        : "memory");
}

extern "C" void kernel_launch(void* const* d_in, const int* in_sizes, int n_in,
                              void* d_out, int out_size)
{
    const float* x = (const float*)d_in[0];
    const float* W = (const float*)d_in[1];
    float* y = (float*)d_out;

    int n_tiles = in_sizes[0] / 16;    // one thread per 4x4 tile (64B)
    int threads = 256;
    int blocks = (n_tiles + threads - 1) / threads;
    subm_conv_tile_v8_kernel<<<blocks, threads>>>(x, W, y, n_tiles);
}